// round 6
// baseline (speedup 1.0000x reference)
#include <cuda_runtime.h>

// ---------------------------------------------------------------------------
// Photonic Clements mesh, N=128. One warp per column; lane t owns rows
// 8t..8t+7 as 8 PACKED complex registers (fma.rn.f32x2 / mul.rn.f32x2 —
// Blackwell packed fp32, only reachable via inline PTX).
// Phase table pre-packs each phase as ((c,c),(-s,s)) so the diagonal layer
// is swap+mul+fma per value. Output serialization identical to round 4/5.
// ---------------------------------------------------------------------------

#define NCOLS   128
#define NLAYERS 255
#define FULL    0xffffffffu

#define AM_  0.97467943448089633f    // sqrt(1-0.05)
#define PP_  0.71063352017759484f    // sqrt(0.5+0.005)
#define QQ_  0.70356236397351441f    // sqrt(0.5-0.005)
#define AMP_ (AM_*PP_)
#define AMQ_ (AM_*QQ_)
#define AX_  0.98994949366116653f    // sqrt(1-0.02)
#define XC_  (AX_*0.1f)                       // aX*sqrt(CT)
#define XS_  (AX_*0.99498743710661995f)       // aX*sqrt(1-CT), corner scalar

typedef unsigned long long ull;

// packed (x=lo, y=hi) helpers
#define PACK2(d, lo, hi)   asm("mov.b64 %0, {%1, %2};" : "=l"(d) : "f"(lo), "f"(hi))
#define UNPACK2(lo, hi, s) asm("mov.b64 {%0, %1}, %2;" : "=f"(lo), "=f"(hi) : "l"(s))
#define SWAP2(d, s) asm("{\n\t.reg .f32 lo, hi;\n\tmov.b64 {lo, hi}, %1;\n\tmov.b64 %0, {hi, lo};\n\t}" : "=l"(d) : "l"(s))
#define FMA2(d, a, b, c) asm("fma.rn.f32x2 %0, %1, %2, %3;" : "=l"(d) : "l"(a), "l"(b), "l"(c))
#define MUL2(d, a, b)    asm("mul.rn.f32x2 %0, %1, %2;" : "=l"(d) : "l"(a), "l"(b))

// phase table: per (layer, port) a ulonglong2 { (c,c), (-s,s) }
__device__ ulonglong2 g_pk[NLAYERS * NCOLS];

__global__ void phase_kernel(const float* __restrict__ theta_even) {
    int i = blockIdx.x * blockDim.x + threadIdx.x;
    if (i < NLAYERS * NCOLS) {
        float s, c;
        sincosf(theta_even[i], &s, &c);
        unsigned int cu = __float_as_uint(c);
        unsigned int su = __float_as_uint(s);
        unsigned int nu = __float_as_uint(-s);
        ulonglong2 e;
        e.x = ((ull)cu << 32) | cu;   // (c, c)
        e.y = ((ull)su << 32) | nu;   // (-s, s)
        g_pk[i] = e;
    }
}

// v *= phase given packed PCC=(c,c), PNS=(-s,s):  v' = PCC*v + PNS*swap(v)
#define CMULP(v, PCC, PNS) do { \
    ull _sv, _t; SWAP2(_sv, v); MUL2(_t, (PNS), _sv); FMA2(v, (PCC), v, _t); } while (0)

// [a;b] <- [[A,iB],[iB,A]][a;b] with KA=(A,A), KNB=(-B,B)
#define MIXP(a, b, KA, KNB) do { \
    ull _sa, _sb, _t, _u; \
    SWAP2(_sb, b); SWAP2(_sa, a); \
    MUL2(_t, (KNB), _sb); MUL2(_u, (KNB), _sa); \
    FMA2(a, (KA), a, _t); \
    FMA2(b, (KA), b, _u); } while (0)

// D layer from slot S (ulonglong2[8]): entries off..off+3 are this layer's phases
#define APPLY_DP(S, off) do { \
    CMULP(v0, (S)[(off)+0].x, (S)[(off)+0].y); \
    CMULP(v2, (S)[(off)+1].x, (S)[(off)+1].y); \
    CMULP(v4, (S)[(off)+2].x, (S)[(off)+2].y); \
    CMULP(v6, (S)[(off)+3].x, (S)[(off)+3].y); } while (0)

#define APPLY_M() do { \
    MIXP(v0, v1, MCC, MNS); \
    MIXP(v2, v3, MCC, MNS); \
    MIXP(v4, v5, MCC, MNS); \
    MIXP(v6, v7, MCC, MNS); } while (0)

#define APPLY_X() do { \
    float _v0x, _v0y, _v7x, _v7y; \
    UNPACK2(_v0x, _v0y, v0); UNPACK2(_v7x, _v7y, v7); \
    float _nb0x = __shfl_down_sync(FULL, _v0x, 1);   /* lane t+1's v0 = row 8t+8 */ \
    float _nb0y = __shfl_down_sync(FULL, _v0y, 1); \
    float _nb7x = __shfl_up_sync  (FULL, _v7x, 1);   /* lane t-1's v7 = row 8t-1 */ \
    float _nb7y = __shfl_up_sync  (FULL, _v7y, 1); \
    MIXP(v1, v2, XCC, XNS); \
    MIXP(v3, v4, XCC, XNS); \
    MIXP(v5, v6, XCC, XNS); \
    ull _snb0, _snb7; \
    PACK2(_snb0, _nb0y, _nb0x);   /* pre-swapped neighbor */ \
    PACK2(_snb7, _nb7y, _nb7x); \
    ull _t7, _t0, _n7, _n0, _c7, _c0; \
    MUL2(_t7, XNS, _snb0); FMA2(_n7, XCC, v7, _t7); \
    MUL2(_t0, XNS, _snb7); FMA2(_n0, XCC, v0, _t0); \
    MUL2(_c7, XSS, v7); MUL2(_c0, XSS, v0); \
    v7 = (t < 31) ? _n7 : _c7;   /* row 255 corner */ \
    v0 = (t > 0)  ? _n0 : _c0;   /* row 0 corner */ } while (0)

#define LD_SLOT(S, ka, kb) do { \
    (S)[0] = g_pk[(ka) * NCOLS + 4 * t + 0]; \
    (S)[1] = g_pk[(ka) * NCOLS + 4 * t + 1]; \
    (S)[2] = g_pk[(ka) * NCOLS + 4 * t + 2]; \
    (S)[3] = g_pk[(ka) * NCOLS + 4 * t + 3]; \
    (S)[4] = g_pk[(kb) * NCOLS + 4 * t + 0]; \
    (S)[5] = g_pk[(kb) * NCOLS + 4 * t + 1]; \
    (S)[6] = g_pk[(kb) * NCOLS + 4 * t + 2]; \
    (S)[7] = g_pk[(kb) * NCOLS + 4 * t + 3]; } while (0)

__global__ void __launch_bounds__(32, 1)
mesh_kernel(const float* __restrict__ theta_in,
            const float* __restrict__ theta_out,
            float* __restrict__ out,
            int mode)   // 1 = real-only (16384 floats), 2 = planar (32768 floats)
{
    const int c = blockIdx.x;    // column (input port)
    const int t = threadIdx.x;   // lane: rows 8t..8t+7

    // packed mixer constants
    ull MCC, MNS, XCC, XNS, XSS;
    PACK2(MCC,  AMP_, AMP_);
    PACK2(MNS, -AMQ_, AMQ_);
    PACK2(XCC,  XC_,  XC_);
    PACK2(XNS, -XS_,  XS_);
    PACK2(XSS,  XS_,  XS_);

    ull z = 0;
    ull v0 = z, v1 = z, v2 = z, v3 = z, v4 = z, v5 = z, v6 = z, v7 = z;

    // --- input: rows 2c, 2c+1 of column c of MMI_IN @ diag(e^{i th_in}) ---
    {
        float s, co;
        sincosf(theta_in[c], &s, &co);
        ull ain, bin;
        PACK2(ain,  AMP_ * co, AMP_ * s);   //  aM*p * e^{i th}
        PACK2(bin, -AMQ_ * s,  AMQ_ * co);  // i*aM*q * e^{i th}
        int slot = 2 * c - 8 * t;
        if      (slot == 0) { v0 = ain; v1 = bin; }
        else if (slot == 2) { v2 = ain; v3 = bin; }
        else if (slot == 4) { v4 = ain; v5 = bin; }
        else if (slot == 6) { v6 = ain; v7 = bin; }
    }

    // --- D0, M, X ---
    {
        ulonglong2 p0[4];
        p0[0] = g_pk[4 * t + 0]; p0[1] = g_pk[4 * t + 1];
        p0[2] = g_pk[4 * t + 2]; p0[3] = g_pk[4 * t + 3];
        APPLY_DP(p0, 0);
        APPLY_M();
        APPLY_X();
    }

    // iteration j (0..125): D(2j+1), M, D(2j+2), M, X; j=126 is the tail.
    // distance-2 double-buffered prefetch, unroll-2.
    ulonglong2 s0[8], s1[8];
    LD_SLOT(s0, 1, 2);
    LD_SLOT(s1, 3, 4);

#pragma unroll 1
    for (int j = 0; j < 126; j += 2) {
        {
            int jn = (j + 2 <= 126) ? (j + 2) : 126;
            ulonglong2 nx[8];
            LD_SLOT(nx, 2 * jn + 1, 2 * jn + 2);
            APPLY_DP(s0, 0);
            APPLY_M();
            APPLY_DP(s0, 4);
            APPLY_M();
            APPLY_X();
#pragma unroll
            for (int m = 0; m < 8; m++) s0[m] = nx[m];
        }
        {
            int jn = (j + 3 <= 126) ? (j + 3) : 126;
            ulonglong2 nx[8];
            LD_SLOT(nx, 2 * jn + 1, 2 * jn + 2);
            APPLY_DP(s1, 0);
            APPLY_M();
            APPLY_DP(s1, 4);
            APPLY_M();
            APPLY_X();
#pragma unroll
            for (int m = 0; m < 8; m++) s1[m] = nx[m];
        }
    }

    // --- tail j=126: D253, M, D254 (slot 0 holds layers 253/254) ---
    APPLY_DP(s0, 0);
    APPLY_M();
    APPLY_DP(s0, 4);

    // --- output rows jj = 4t..4t+3: MMI_OUT pair reduce, then e^{i th_out} ---
#define OUTP(va, vb, jj) do { \
        float _ax, _ay, _bx, _by; \
        UNPACK2(_ax, _ay, va); UNPACK2(_bx, _by, vb); \
        float _ox = fmaf(AMP_, _ax, -AMQ_ * _by); \
        float _oy = fmaf(AMP_, _ay,  AMQ_ * _bx); \
        float _so, _co; sincosf(theta_out[jj], &_so, &_co); \
        float _re = _ox * _co - _oy * _so; \
        float _im = _ox * _so + _oy * _co; \
        if (mode == 1) { out[(jj) * NCOLS + c] = _re; } \
        else { out[(jj) * NCOLS + c] = _re; \
               out[NCOLS * NCOLS + (jj) * NCOLS + c] = _im; } } while (0)

    OUTP(v0, v1, 4 * t);
    OUTP(v2, v3, 4 * t + 1);
    OUTP(v4, v5, 4 * t + 2);
    OUTP(v6, v7, 4 * t + 3);
#undef OUTP
}

extern "C" void kernel_launch(void* const* d_in, const int* in_sizes, int n_in,
                              void* d_out, int out_size) {
    // Inputs identified by SIZE (theta_even = unique 32640-elem array;
    // theta_in precedes theta_out).
    const float* th_ev  = nullptr;
    const float* small_[2] = {nullptr, nullptr};
    int ns = 0;
    for (int i = 0; i < n_in && i < 3; i++) {
        if (in_sizes[i] > 1000) th_ev = (const float*)d_in[i];
        else if (ns < 2)        small_[ns++] = (const float*)d_in[i];
    }
    const float* th_in  = small_[0];
    const float* th_out = small_[1];

    int mode = (out_size == NCOLS * NCOLS) ? 1 : 2;  // 16384 -> real-only, else planar

    phase_kernel<<<(NLAYERS * NCOLS + 255) / 256, 256>>>(th_ev);
    mesh_kernel<<<NCOLS, 32>>>(th_in, th_out, (float*)d_out, mode);
}